// round 5
// baseline (speedup 1.0000x reference)
#include <cuda_runtime.h>
#include <math.h>
#include <stdint.h>

// Problem constants
constexpr int Bc  = 4;
constexpr int Sc  = 2048;
constexpr int Dc  = 1024;
constexpr int Hc  = 16;
constexpr int DKc = 64;
constexpr int Mrows = Bc * Sc;     // 8192
constexpr int Ec    = Hc * DKc;    // 1024

// Scratch (device globals: allocation-free per harness rules). 4 x 32 MiB.
__device__ float g_Q[Mrows * Ec];
__device__ float g_K[Mrows * Ec];
__device__ float g_V[Mrows * Ec];
__device__ float g_Ctx[Mrows * Ec];

// ---------------------------------------------------------------------------
// Tiled SGEMM body: C[m][n] = sum_k A[m][k] * W[n][k]   (A: MxK rm, W: NxK rm)
// 64x64 tile, BK=16, 256 threads, 4x4 per-thread register block.
// ---------------------------------------------------------------------------
__device__ __forceinline__ void gemm64_body(const float* __restrict__ A,
                                            const float* __restrict__ W,
                                            float* __restrict__ C,
                                            int K, int N)
{
    __shared__ float As[16 * 64];   // As[k][m]
    __shared__ float Bs[16 * 64];   // Bs[k][n]

    const int tid = threadIdx.x;
    const int ty  = tid >> 4;       // 0..15
    const int tx  = tid & 15;       // 0..15
    const int m0  = blockIdx.y * 64;
    const int n0  = blockIdx.x * 64;

    float acc[4][4] = {};

    const int lm = tid >> 2;          // 0..63  (row within tile)
    const int lk = (tid & 3) << 2;    // 0,4,8,12

    const float* Ap = A + (size_t)(m0 + lm) * K + lk;
    const float* Wp = W + (size_t)(n0 + lm) * K + lk;

    for (int kk = 0; kk < K; kk += 16) {
        float4 av = *reinterpret_cast<const float4*>(Ap + kk);
        float4 wv = *reinterpret_cast<const float4*>(Wp + kk);
        As[(lk + 0) * 64 + lm] = av.x;
        As[(lk + 1) * 64 + lm] = av.y;
        As[(lk + 2) * 64 + lm] = av.z;
        As[(lk + 3) * 64 + lm] = av.w;
        Bs[(lk + 0) * 64 + lm] = wv.x;
        Bs[(lk + 1) * 64 + lm] = wv.y;
        Bs[(lk + 2) * 64 + lm] = wv.z;
        Bs[(lk + 3) * 64 + lm] = wv.w;
        __syncthreads();

        #pragma unroll
        for (int k = 0; k < 16; ++k) {
            float4 a4 = *reinterpret_cast<const float4*>(&As[k * 64 + ty * 4]);
            float4 b4 = *reinterpret_cast<const float4*>(&Bs[k * 64 + tx * 4]);
            float a[4] = {a4.x, a4.y, a4.z, a4.w};
            float b[4] = {b4.x, b4.y, b4.z, b4.w};
            #pragma unroll
            for (int i = 0; i < 4; ++i)
                #pragma unroll
                for (int j = 0; j < 4; ++j)
                    acc[i][j] = fmaf(a[i], b[j], acc[i][j]);
        }
        __syncthreads();
    }

    #pragma unroll
    for (int i = 0; i < 4; ++i) {
        float4 cv = make_float4(acc[i][0], acc[i][1], acc[i][2], acc[i][3]);
        *reinterpret_cast<float4*>(&C[(size_t)(m0 + ty * 4 + i) * N + n0 + tx * 4]) = cv;
    }
}

// QKV projection: grid (Ec/64, Mrows/64, 3); z selects which projection.
__global__ __launch_bounds__(256) void qkv_gemm(const float* __restrict__ X,
                                                const float* __restrict__ Wq,
                                                const float* __restrict__ Wk,
                                                const float* __restrict__ Wv)
{
    const float* W = (blockIdx.z == 0) ? Wq : (blockIdx.z == 1) ? Wk : Wv;
    float* C       = (blockIdx.z == 0) ? g_Q : (blockIdx.z == 1) ? g_K : g_V;
    gemm64_body(X, W, C, Dc, Ec);
}

// Output projection: out = ctx @ Wo^T
__global__ __launch_bounds__(256) void out_gemm(const float* __restrict__ Wo,
                                                float* __restrict__ out)
{
    gemm64_body(g_Ctx, Wo, out, Ec, Dc);
}

// ---------------------------------------------------------------------------
// Flash attention, fp32, BQ=64, BKV=64, online softmax, causal tile skipping.
// Q/K/V layout: [b][s][h*64+dk] (row stride Ec=1024).
// grid: (Sc/64, Bc*Hc), 256 threads.
// ---------------------------------------------------------------------------
__global__ __launch_bounds__(256) void attn_fwd(const float* __restrict__ mask)
{
    __shared__ float Qs [64 * 64];   // Qs[r][dk]
    __shared__ float KPs[64 * 65];   // K tile [c][dk] (stride 65), reused as P [r][c]
    __shared__ float Vs [64 * 64];   // V tile [c][dk]

    const int tid = threadIdx.x;
    const int ty  = tid >> 4;        // 0..15
    const int tx  = tid & 15;        // 0..15
    const int qt  = blockIdx.x;
    const int q0  = qt * 64;
    const int bh  = blockIdx.y;
    const int b   = bh >> 4;
    const int h   = bh & 15;

    const size_t rowbase = (size_t)(b * Sc) * Ec + (size_t)h * DKc;

    // Load Q tile (64 x 64)
    #pragma unroll
    for (int i = 0; i < 16; ++i) {
        int e = i * 256 + tid;
        int r = e >> 6, dk = e & 63;
        Qs[r * 64 + dk] = g_Q[rowbase + (size_t)(q0 + r) * Ec + dk];
    }

    float m_i[4], l_i[4], o[4][4];
    #pragma unroll
    for (int i = 0; i < 4; ++i) {
        m_i[i] = -3.0e38f;
        l_i[i] = 0.0f;
        #pragma unroll
        for (int j = 0; j < 4; ++j) o[i][j] = 0.0f;
    }

    // Causal skip: mask already encodes causality+evidence; tiles with
    // kv0 > q0+63 are fully -1e9 -> contribute nothing -> skip them.
    for (int t = 0; t <= qt; ++t) {
        const int kv0 = t * 64;

        __syncthreads();  // previous PV reads of KPs/Vs are complete
        #pragma unroll
        for (int i = 0; i < 16; ++i) {
            int e = i * 256 + tid;
            int r = e >> 6, dk = e & 63;
            size_t g = rowbase + (size_t)(kv0 + r) * Ec + dk;
            KPs[r * 65 + dk] = g_K[g];
            Vs [r * 64 + dk] = g_V[g];
        }
        __syncthreads();  // also orders the Qs stores on the first iteration

        // S = Q K^T  (thread owns rows ty*4+i, cols tx*4+j)
        float s[4][4] = {};
        #pragma unroll 8
        for (int dk = 0; dk < 64; ++dk) {
            float a0 = Qs[(ty * 4 + 0) * 64 + dk];
            float a1 = Qs[(ty * 4 + 1) * 64 + dk];
            float a2 = Qs[(ty * 4 + 2) * 64 + dk];
            float a3 = Qs[(ty * 4 + 3) * 64 + dk];
            float b0 = KPs[(tx * 4 + 0) * 65 + dk];
            float b1 = KPs[(tx * 4 + 1) * 65 + dk];
            float b2 = KPs[(tx * 4 + 2) * 65 + dk];
            float b3 = KPs[(tx * 4 + 3) * 65 + dk];
            s[0][0] = fmaf(a0, b0, s[0][0]); s[0][1] = fmaf(a0, b1, s[0][1]);
            s[0][2] = fmaf(a0, b2, s[0][2]); s[0][3] = fmaf(a0, b3, s[0][3]);
            s[1][0] = fmaf(a1, b0, s[1][0]); s[1][1] = fmaf(a1, b1, s[1][1]);
            s[1][2] = fmaf(a1, b2, s[1][2]); s[1][3] = fmaf(a1, b3, s[1][3]);
            s[2][0] = fmaf(a2, b0, s[2][0]); s[2][1] = fmaf(a2, b1, s[2][1]);
            s[2][2] = fmaf(a2, b2, s[2][2]); s[2][3] = fmaf(a2, b3, s[2][3]);
            s[3][0] = fmaf(a3, b0, s[3][0]); s[3][1] = fmaf(a3, b1, s[3][1]);
            s[3][2] = fmaf(a3, b2, s[3][2]); s[3][3] = fmaf(a3, b3, s[3][3]);
        }

        // scale + mask + row max (reduce over the 16 tx lanes; warp holds
        // 2 ty values in lanes [0:16) and [16:32), xor<16 stays in-half)
        const float* mrow = mask + (size_t)(q0 + ty * 4) * Sc + kv0 + tx * 4;
        float mnew[4];
        #pragma unroll
        for (int i = 0; i < 4; ++i) {
            float mx = -3.0e38f;
            #pragma unroll
            for (int j = 0; j < 4; ++j) {
                s[i][j] = s[i][j] * 0.125f + mrow[(size_t)i * Sc + j];
                mx = fmaxf(mx, s[i][j]);
            }
            #pragma unroll
            for (int off = 8; off; off >>= 1)
                mx = fmaxf(mx, __shfl_xor_sync(0xffffffffu, mx, off));
            mnew[i] = fmaxf(m_i[i], mx);
        }

        __syncthreads();  // all reads of K data in KPs are done -> reuse as P

        #pragma unroll
        for (int i = 0; i < 4; ++i) {
            float alpha = __expf(m_i[i] - mnew[i]);
            float rs = 0.0f;
            #pragma unroll
            for (int j = 0; j < 4; ++j) {
                float p = __expf(s[i][j] - mnew[i]);
                KPs[(ty * 4 + i) * 65 + tx * 4 + j] = p;   // P[r][c]
                rs += p;
            }
            #pragma unroll
            for (int off = 8; off; off >>= 1)
                rs += __shfl_xor_sync(0xffffffffu, rs, off);
            l_i[i] = l_i[i] * alpha + rs;
            m_i[i] = mnew[i];
            o[i][0] *= alpha; o[i][1] *= alpha; o[i][2] *= alpha; o[i][3] *= alpha;
        }
        __syncthreads();  // P visible to all

        // O += P @ V  (thread owns rows ty*4+i, dk cols tx*4+j)
        #pragma unroll 8
        for (int c = 0; c < 64; ++c) {
            float4 vb = *reinterpret_cast<const float4*>(&Vs[c * 64 + tx * 4]);
            #pragma unroll
            for (int i = 0; i < 4; ++i) {
                float p = KPs[(ty * 4 + i) * 65 + c];
                o[i][0] = fmaf(p, vb.x, o[i][0]);
                o[i][1] = fmaf(p, vb.y, o[i][1]);
                o[i][2] = fmaf(p, vb.z, o[i][2]);
                o[i][3] = fmaf(p, vb.w, o[i][3]);
            }
        }
    }

    // Normalize and store ctx[b][s][h*64+dk]
    #pragma unroll
    for (int i = 0; i < 4; ++i) {
        float inv = 1.0f / l_i[i];
        float4 cv = make_float4(o[i][0] * inv, o[i][1] * inv,
                                o[i][2] * inv, o[i][3] * inv);
        *reinterpret_cast<float4*>(
            &g_Ctx[rowbase + (size_t)(q0 + ty * 4 + i) * Ec + tx * 4]) = cv;
    }
}

// ---------------------------------------------------------------------------
// Launch
// ---------------------------------------------------------------------------
extern "C" void kernel_launch(void* const* d_in, const int* in_sizes, int n_in,
                              void* d_out, int out_size)
{
    (void)in_sizes; (void)n_in; (void)out_size;
    const float* hs   = (const float*)d_in[0];  // hidden_states (B,S,D)
    const float* mask = (const float*)d_in[1];  // attention_mask (S,S)
    const float* Wq   = (const float*)d_in[2];  // (H*DK, D)
    const float* Wk   = (const float*)d_in[3];
    const float* Wv   = (const float*)d_in[4];
    const float* Wo   = (const float*)d_in[5];  // (D, H*DK)
    float* out        = (float*)d_out;          // (B,S,D)

    dim3 gQKV(Ec / 64, Mrows / 64, 3);
    qkv_gemm<<<gQKV, 256>>>(hs, Wq, Wk, Wv);

    dim3 gAttn(Sc / 64, Bc * Hc);
    attn_fwd<<<gAttn, 256>>>(mask);

    dim3 gOut(Dc / 64, Mrows / 64);
    out_gemm<<<gOut, 256>>>(Wo, out);
}